// round 16
// baseline (speedup 1.0000x reference)
#include <cuda_runtime.h>
#include <cuda_bf16.h>

#define DIM        128
#define MAX_ENT    50048
#define MAX_REL    24
#define HASH_SZ    8192
#define HASH_MASK  8191
#define GROUPS     8
#define EPT        8             // edges per thread in the scan

// ---------------- device scratch (static zero-init == "clean" state) ------
// Hash table (parity double-buffered): key = node+1 (0 = empty), slot = bucket.
// Parity invariants (call N, par = epoch&1, epoch bumped at END of k_oc):
//   scan  : inserts into key[par]/list[par]/list_n[par] (zeroed by call N-1 oc)
//   gemm  : reads list/key[par], accumulates agg[par] (zeroed by call N-1 oc),
//           snapshots nprev = list_n[1-par]
//   oc    : reads key/agg/list[par]; cleans msg/cnt (own buckets), and
//           agg/key/list_n[1-par] via list[1-par] (call N-1's, still intact)
__device__ unsigned int g_epoch;
__device__ int          g_key[2][HASH_SZ];
__device__ int          g_list[2][HASH_SZ];
__device__ int          g_list_n[2];
__device__ int          g_nn_prev;                   // written by gemm
__device__ float        g_msg[(size_t)HASH_SZ * MAX_REL * DIM];
__device__ float        g_cnt[HASH_SZ * MAX_REL];
__device__ float        g_agg[2][HASH_SZ * DIM];

__device__ __forceinline__ int ld_idx(const void* p, size_t i, int is64) {
    if (is64) return (int)((const long long*)p)[i];
    return ((const int*)p)[i];
}

// fast tanh: 1 - 2/(e^{2x}+1); rel err ~1e-7
__device__ __forceinline__ float ftanh(float x) {
    float e = __expf(2.0f * x);
    return 1.0f - 2.0f / (e + 1.0f);
}

// PDL primitives (sm_90+). Triggers at KERNEL ENTRY: trigger only gates the
// dependent's LAUNCH; ordering/visibility comes solely from
// griddepcontrol.wait. Every pre-wait section reads ONLY kernel inputs.
__device__ __forceinline__ void pdl_wait() {
    asm volatile("griddepcontrol.wait;" ::: "memory");
}
__device__ __forceinline__ void pdl_trigger() {
    asm volatile("griddepcontrol.launch_dependents;");
}

// Concurrent get-or-create: returns the unique bucket for node this call.
__device__ __forceinline__ int slot_get_or_create(int par, int node) {
    unsigned int b = (unsigned int)node & HASH_MASK;
    while (true) {
        int k = g_key[par][b];
        if (k == node + 1) return (int)b;
        if (k == 0) {
            int old = atomicCAS(&g_key[par][b], 0, node + 1);
            if (old == 0) {
                int idx = atomicAdd(&g_list_n[par], 1);
                g_list[par][idx] = (int)b;
                return (int)b;
            }
            if (old == node + 1) return (int)b;
        }
        b = (b + 1) & HASH_MASK;
    }
}

// Lookup (node guaranteed inserted by scan).
__device__ __forceinline__ int slot_lookup(int par, int node) {
    unsigned int b = (unsigned int)node & HASH_MASK;
    while (g_key[par][b] != node + 1) b = (b + 1) & HASH_MASK;
    return (int)b;
}

// ============ 1) k_scan: NO predecessor. SMEM membership bitmap + hash =====
// grid = ceil(n_edge / (EPT*256)) blocks of 256.
__global__ void __launch_bounds__(256)
k_scan(const void* __restrict__ edge_index,
       const void* __restrict__ edge_type,
       const float* __restrict__ x,
       const void* __restrict__ sample,
       int n_edge, int n_rel, int batch) {
    pdl_trigger();                       // k_gemm may stage W during our body
    __shared__ unsigned int bitmap[MAX_ENT / 32];   // 6.3 KB, exact membership
    __shared__ int s_any_e, s_any_s;
    const int tid = threadIdx.x;

    // zero bitmap + dtype detects (inputs only)
    for (int i = tid; i < MAX_ENT / 32; i += 256) bitmap[i] = 0u;
    if (tid == 0) { s_any_e = 0; s_any_s = 0; }
    __syncthreads();
    if (((const unsigned int*)edge_index)[tid * 2 + 1] != 0u) atomicOr(&s_any_e, 1);
    if (((const unsigned int*)sample)[tid * 2 + 1] != 0u)     atomicOr(&s_any_s, 1);
    __syncthreads();
    const int is64  = s_any_e ? 0 : 1;   // edge arrays dtype
    const int is64s = s_any_s ? 0 : 1;   // sample dtype

    // prologue: independent dst loads (MLP 2-4)
    const int t  = blockIdx.x * 256 + tid;
    const int e0 = t * EPT;
    int dst[EPT];
    int n = 0;
    if (e0 < n_edge) {
        n = (e0 + EPT <= n_edge) ? EPT : (n_edge - e0);
        if (n == EPT) {
            if (!is64) {
                const int4* p = (const int4*)((const int*)edge_index + (size_t)n_edge + e0);
                int4 v0 = p[0], v1 = p[1];
                dst[0]=v0.x; dst[1]=v0.y; dst[2]=v0.z; dst[3]=v0.w;
                dst[4]=v1.x; dst[5]=v1.y; dst[6]=v1.z; dst[7]=v1.w;
            } else {
                const longlong2* p = (const longlong2*)((const long long*)edge_index + (size_t)n_edge + e0);
                longlong2 w0 = p[0], w1 = p[1], w2 = p[2], w3 = p[3];
                dst[0]=(int)w0.x; dst[1]=(int)w0.y; dst[2]=(int)w1.x; dst[3]=(int)w1.y;
                dst[4]=(int)w2.x; dst[5]=(int)w2.y; dst[6]=(int)w3.x; dst[7]=(int)w3.y;
            }
        } else {
            for (int k = 0; k < n; k++)
                dst[k] = ld_idx(edge_index, (size_t)n_edge + e0 + k, is64);
        }
    }

    // build exact membership bitmap from sample cols 0,2 (16 iters/thread)
    for (int i = tid; i < batch * 2; i += 256) {
        int b = i >> 1;
        int c = (i & 1) * 2;
        int node = ld_idx(sample, (size_t)b * 3 + c, is64s);
        atomicOr(&bitmap[node >> 5], 1u << (node & 31));
    }
    __syncthreads();

    const int par = (int)(g_epoch & 1u);   // stable: bumped by previous oc

    // global hash insertion of all sample nodes (threads t < batch*2)
    if (t < batch * 2) {
        int b = t >> 1;
        int c = (t & 1) * 2;
        int node = ld_idx(sample, (size_t)b * 3 + c, is64s);
        slot_get_or_create(par, node);
    }

    // probe (SMEM, 29 cyc) + sparse accumulate for hits
    if (n > 0) {
        unsigned int hit = 0;
#pragma unroll
        for (int k = 0; k < EPT; k++) {
            if (k < n && ((bitmap[dst[k] >> 5] >> (dst[k] & 31)) & 1u))
                hit |= 1u << k;
        }
        while (hit) {
            int k = __ffs(hit) - 1;
            hit &= hit - 1;
            int s = slot_get_or_create(par, dst[k]);
            int e   = e0 + k;
            int r   = ld_idx(edge_type, e, is64);
            int src = ld_idx(edge_index, e, is64);
            atomicAdd(&g_cnt[s * n_rel + r], 1.0f);
            const float4* xs = (const float4*)(x + (size_t)src * DIM);
            float* m = &g_msg[((size_t)s * n_rel + r) * DIM];
#pragma unroll
            for (int j = 0; j < DIM / 4; j++) {
                float4 v = xs[j];
                atomicAdd(&m[4 * j + 0], v.x);
                atomicAdd(&m[4 * j + 1], v.y);
                atomicAdd(&m[4 * j + 2], v.z);
                atomicAdd(&m[4 * j + 3], v.w);
            }
        }
    }
}

// ============ 2) k_gemm: prologue W staging | wait | compute ===============
// grid = (n_rel + 1) * 2 * GROUPS blocks of 128 threads.
__global__ void __launch_bounds__(128)
k_gemm(const float* __restrict__ W_rel,
       const float* __restrict__ W_root,
       const float* __restrict__ x,
       int n_rel) {
    pdl_trigger();                       // k_oc may start its prologue now
    __shared__ float Ws[64 * DIM];       // one 64-col half, Ws[d * 64 + c]
    __shared__ float ms[DIM];

    int idx  = blockIdx.x;
    int r    = idx % (n_rel + 1);
    int half = (idx / (n_rel + 1)) & 1;
    int sg   = idx / ((n_rel + 1) * 2);
    const float* W = (r < n_rel) ? (W_rel + (size_t)r * DIM * DIM) : W_root;
    int tid = threadIdx.x;

    // prologue: stage W tile (input-only; overlaps scan's whole body)
    int fbase = half * 64;
    for (int i = tid; i < 64 * DIM / 4; i += 128) {
        int d = i >> 4, c4 = i & 15;
        ((float4*)Ws)[d * 16 + c4] = *(const float4*)&W[d * DIM + fbase + c4 * 4];
    }
    __syncthreads();

    pdl_wait();                          // scan's hash/msg/cnt now visible
    const int par = (int)(g_epoch & 1u);
    int nn = g_list_n[par];
    if (idx == 0 && tid == 0) g_nn_prev = g_list_n[1 - par];  // snapshot for oc
    float* agg = g_agg[par];

    int c  = tid & 63;
    int dh = (tid >> 6) * 64;

    for (int s = sg; s < nn; s += GROUPS) {
        int b = g_list[par][s];
        bool skip = false;
        float scale = 1.0f;
        if (r < n_rel) {
            float cnt = g_cnt[b * n_rel + r];    // uniform across block
            if (cnt == 0.0f) skip = true;
            else scale = 1.0f / cnt;
        }
        if (!skip) {
            if (r < n_rel)
                ms[tid] = g_msg[((size_t)b * n_rel + r) * DIM + tid] * scale;
            else {
                int node = g_key[par][b] - 1;
                ms[tid] = x[(size_t)node * DIM + tid];
            }
        }
        __syncthreads();
        if (!skip) {
            float acc = 0.0f;
#pragma unroll
            for (int k = 0; k < 16; k++) {
                int d = dh + k * 4;
                float4 mv = *(const float4*)&ms[d];
                acc += mv.x * Ws[(d + 0) * 64 + c];
                acc += mv.y * Ws[(d + 1) * 64 + c];
                acc += mv.z * Ws[(d + 2) * 64 + c];
                acc += mv.w * Ws[(d + 3) * 64 + c];
            }
            atomicAdd(&agg[b * DIM + fbase + c], acc);
        }
        __syncthreads();
    }
}

// ============ 3) k_oc: prologue INPUT gathers | wait | out ∥ cleanup =======
// out reads key/agg[par]; cleanup touches msg/cnt (own buckets, gemm-done)
// and agg/key/list_n[1-par] via list[1-par] — zero intra-kernel races.
// grid = 256 blocks x 256 (batch warps).
__global__ void __launch_bounds__(256)
k_oc(const void* __restrict__ sample,
     const float* __restrict__ init_rel,
     float* __restrict__ out,
     int batch, int n_rel) {
    const int tid  = threadIdx.x;
    const int gtid = blockIdx.x * 256 + tid;
    const int gsz  = gridDim.x * 256;

    // prologue: sample dtype detect + h/rel/t + init_rel gathers (inputs only)
    int is64s;
    {
        unsigned int hw = ((const unsigned int*)sample)[((tid & 31) * 7 + 1) * 2 + 1];
        unsigned int any = __ballot_sync(0xffffffffu, hw != 0u);
        is64s = any ? 0 : 1;
    }
    int w    = gtid >> 5;
    int lane = tid & 31;
    int h = 0, q = 0;
    float4 rv = make_float4(0.f, 0.f, 0.f, 0.f);
    if (w < batch) {
        int rel = 0;
        if (lane == 0) {
            h   = ld_idx(sample, (size_t)w * 3 + 0, is64s);
            rel = ld_idx(sample, (size_t)w * 3 + 1, is64s);
            q   = ld_idx(sample, (size_t)w * 3 + 2, is64s);
        }
        h   = __shfl_sync(0xffffffffu, h, 0);
        q   = __shfl_sync(0xffffffffu, q, 0);
        rel = __shfl_sync(0xffffffffu, rel, 0);
        rv  = ((const float4*)init_rel)[rel * (DIM / 4) + lane];
    }

    pdl_wait();                          // gemm's agg + scan's hash visible

    const int par   = (int)(g_epoch & 1u);
    const int nn    = g_list_n[par];     // zeroed only by NEXT call's oc
    const int nprev = g_nn_prev;         // snapshotted by gemm this call

    // ---- out (hash lookup on key[par]; never touches 1-par state) ---------
    if (w < batch) {
        int sh = 0, st = 0;
        if (lane == 0) { sh = slot_lookup(par, h); st = slot_lookup(par, q); }
        sh = __shfl_sync(0xffffffffu, sh, 0);
        st = __shfl_sync(0xffffffffu, st, 0);
        const float4* agg4 = (const float4*)g_agg[par];
        float4 ah = agg4[sh * (DIM / 4) + lane];
        float4 at = agg4[st * (DIM / 4) + lane];
        float4 o;
        o.x = ftanh(ah.x) * (rv.x * ftanh(at.x));
        o.y = ftanh(ah.y) * (rv.y * ftanh(at.y));
        o.z = ftanh(ah.z) * (rv.z * ftanh(at.z));
        o.w = ftanh(ah.w) * (rv.w * ftanh(at.w));
        ((float4*)out)[(size_t)w * (DIM / 4) + lane] = o;
    }

    // ---- cleanup, concurrent with out (disjoint data) ----------------------
    {
        float4 z = make_float4(0.f, 0.f, 0.f, 0.f);
        // own buckets: msg/cnt (consumed by gemm already)
        for (int i = gtid; i < nn * n_rel; i += gsz) {
            int b = g_list[par][i / n_rel];
            int r = i % n_rel;
            float4* m4 = (float4*)&g_msg[((size_t)b * n_rel + r) * DIM];
#pragma unroll
            for (int j = 0; j < DIM / 4; j++) m4[j] = z;
            g_cnt[b * n_rel + r] = 0.0f;
        }
        // previous call's buckets: agg[1-par] + key[1-par] (next call's buffer)
        float4* aggp = (float4*)g_agg[1 - par];
        for (int i = gtid; i < nprev; i += gsz) {
            int b = g_list[1 - par][i];
#pragma unroll
            for (int j = 0; j < DIM / 4; j++) aggp[b * (DIM / 4) + j] = z;
            g_key[1 - par][b] = 0;
        }
        if (gtid == 0) {
            g_list_n[1 - par] = 0;       // next call's insert counter
            atomicAdd(&g_epoch, 1u);     // next call's parity (graphs serialize)
        }
    }
}

// ---------------- launch (PDL-chained, 3 stages) ----------------
template <typename... Args>
static inline void launch_pdl(void (*kern)(Args...), dim3 grid, dim3 block,
                              bool pdl_secondary, Args... args) {
    cudaLaunchConfig_t cfg = {};
    cfg.gridDim = grid;
    cfg.blockDim = block;
    cfg.dynamicSmemBytes = 0;
    cfg.stream = 0;
    cudaLaunchAttribute attr[1];
    if (pdl_secondary) {
        attr[0].id = cudaLaunchAttributeProgrammaticStreamSerialization;
        attr[0].val.programmaticStreamSerializationAllowed = 1;
        cfg.attrs = attr;
        cfg.numAttrs = 1;
    }
    cudaLaunchKernelEx(&cfg, kern, args...);
}

extern "C" void kernel_launch(void* const* d_in, const int* in_sizes, int n_in,
                              void* d_out, int out_size) {
    const float* init_embed = (const float*)d_in[0];
    const float* init_rel   = (const float*)d_in[1];
    const float* W_rel      = (const float*)d_in[2];
    const float* W_root     = (const float*)d_in[3];
    const void*  edge_index = d_in[4];
    const void*  edge_type  = d_in[5];
    const void*  sample     = d_in[6];
    float* out = (float*)d_out;

    int n_rel  = in_sizes[1] / DIM;
    int n_edge = in_sizes[5];
    int batch  = in_sizes[6] / 3;

    launch_pdl(k_scan, dim3((n_edge + EPT * 256 - 1) / (EPT * 256)), dim3(256), false,
               edge_index, edge_type, (const float*)init_embed, sample,
               n_edge, n_rel, batch);
    launch_pdl(k_gemm, dim3((n_rel + 1) * 2 * GROUPS), dim3(128), true,
               W_rel, W_root, (const float*)init_embed, n_rel);
    launch_pdl(k_oc, dim3(256), dim3(256), true,
               sample, (const float*)init_rel, out, batch, n_rel);
}

// round 17
// speedup vs baseline: 1.4307x; 1.4307x over previous
#include <cuda_runtime.h>
#include <cuda_bf16.h>

#define DIM        128
#define MAX_ENT    50048
#define MAX_REL    24
#define MAX_NEEDED 4096
#define MAX_BATCH  4096
#define GROUPS     16
#define EPT        8             // edges per thread in the scan

// ---------------- device scratch (static zero-init == "clean" state) ------
// g_slot[node]: 0 = free, 1 = being claimed, s+2 = assigned slot s
__device__ unsigned int g_epoch;                     // bumped once per call (k_mark)
__device__ int          g_is64;
__device__ int          g_slot[MAX_ENT];
__device__ unsigned int g_bits[MAX_ENT / 32];        // membership bitmap
__device__ int          g_needed_nodes[MAX_NEEDED];
__device__ int          g_n_needed;                  // live counter (mark writes)
__device__ int          g_nn_copy;                   // snapshot (scan writes)
__device__ int          g_hs[MAX_BATCH];             // translated head slots
__device__ int          g_ts[MAX_BATCH];             // translated tail slots
__device__ float        g_msg[(size_t)MAX_NEEDED * MAX_REL * DIM];
__device__ float        g_cnt[MAX_NEEDED * MAX_REL];
__device__ float        g_agg[2][MAX_NEEDED * DIM];  // parity double-buffer

__device__ __forceinline__ int ld_idx(const void* p, size_t i, int is64) {
    if (is64) return (int)((const long long*)p)[i];
    return ((const int*)p)[i];
}

// fast tanh: 1 - 2/(e^{2x}+1); rel err ~1e-7
__device__ __forceinline__ float ftanh(float x) {
    float e = __expf(2.0f * x);
    return 1.0f - 2.0f / (e + 1.0f);
}

// PDL primitives (sm_90+). Triggers at KERNEL ENTRY: trigger only gates the
// dependent's LAUNCH; ordering/visibility comes solely from
// griddepcontrol.wait. Hence every pre-wait section reads ONLY kernel inputs.
__device__ __forceinline__ void pdl_wait() {
    asm volatile("griddepcontrol.wait;" ::: "memory");
}
__device__ __forceinline__ void pdl_trigger() {
    asm volatile("griddepcontrol.launch_dependents;");
}

// ============ 1) k_mark: epoch bump + dtype detect + mark + compact ========
__global__ void k_mark(const unsigned int* __restrict__ ei_words,
                       const void* __restrict__ sample, int batch) {
    pdl_trigger();                       // k_scan may start its prologue now
    __shared__ int s_any;
    if (threadIdx.x == 0) s_any = 0;
    __syncthreads();
    if (ei_words[threadIdx.x * 2 + 1] != 0u) atomicOr(&s_any, 1);
    __syncthreads();
    int is64 = s_any ? 0 : 1;
    if (blockIdx.x == 0 && threadIdx.x == 0) {
        g_is64 = is64;
        atomicAdd(&g_epoch, 1u);         // nothing else reads epoch this kernel
    }

    int i = blockIdx.x * blockDim.x + threadIdx.x;
    if (i < batch * 2) {
        int b = i >> 1;
        int c = (i & 1) * 2;                        // sample columns 0 and 2
        int node = ld_idx(sample, (size_t)b * 3 + c, is64);
        if (atomicCAS(&g_slot[node], 0, 1) == 0) {  // unique claimer
            int s = atomicAdd(&g_n_needed, 1);
            g_needed_nodes[s] = node;
            atomicOr(&g_bits[node >> 5], 1u << (node & 31));
            g_slot[node] = s + 2;
        }
    }
}

// ============ 2) k_scan: prologue dst loads | wait | translate + scan ======
__global__ void __launch_bounds__(256)
k_scan(const void* __restrict__ edge_index,
       const void* __restrict__ edge_type,
       const float* __restrict__ x,
       const void* __restrict__ sample,
       int n_edge, int n_rel, int batch) {
    pdl_trigger();                       // k_gemm may stage W during our body
    __shared__ int s_any;
    const int tid = threadIdx.x;

    // local dtype detect (input-only)
    if (tid == 0) s_any = 0;
    __syncthreads();
    if (((const unsigned int*)edge_index)[tid * 2 + 1] != 0u) atomicOr(&s_any, 1);
    __syncthreads();
    const int is64 = s_any ? 0 : 1;

    // prologue: independent dst loads (overlap with k_mark's whole body)
    const int t  = blockIdx.x * 256 + tid;
    const int e0 = t * EPT;
    int dst[EPT];
    int n = 0;
    if (e0 < n_edge) {
        n = (e0 + EPT <= n_edge) ? EPT : (n_edge - e0);
        if (n == EPT) {
            if (!is64) {
                const int4* p = (const int4*)((const int*)edge_index + (size_t)n_edge + e0);
                int4 v0 = p[0], v1 = p[1];
                dst[0]=v0.x; dst[1]=v0.y; dst[2]=v0.z; dst[3]=v0.w;
                dst[4]=v1.x; dst[5]=v1.y; dst[6]=v1.z; dst[7]=v1.w;
            } else {
                const longlong2* p = (const longlong2*)((const long long*)edge_index + (size_t)n_edge + e0);
                longlong2 w0 = p[0], w1 = p[1], w2 = p[2], w3 = p[3];
                dst[0]=(int)w0.x; dst[1]=(int)w0.y; dst[2]=(int)w1.x; dst[3]=(int)w1.y;
                dst[4]=(int)w2.x; dst[5]=(int)w2.y; dst[6]=(int)w3.x; dst[7]=(int)w3.y;
            }
        } else {
            for (int k = 0; k < n; k++)
                dst[k] = ld_idx(edge_index, (size_t)n_edge + e0 + k, is64);
        }
    }

    pdl_wait();                          // mark's slot/bits now visible

    // sample -> slot translation (slots final now); snapshot nn for later
    // kernels so k_oc can reset the live counter without a read race.
    if (t < batch) {
        int h = ld_idx(sample, (size_t)t * 3 + 0, is64);
        int q = ld_idx(sample, (size_t)t * 3 + 2, is64);
        g_hs[t] = g_slot[h] - 2;
        g_ts[t] = g_slot[q] - 2;
    }
    if (t == 0) g_nn_copy = g_n_needed;

    if (n > 0) {
        unsigned int hit = 0;
#pragma unroll
        for (int k = 0; k < EPT; k++) {
            if (k < n && ((g_bits[dst[k] >> 5] >> (dst[k] & 31)) & 1u))
                hit |= 1u << k;
        }
        while (hit) {
            int k = __ffs(hit) - 1;
            hit &= hit - 1;
            int s = g_slot[dst[k]] - 2;
            int e   = e0 + k;
            int r   = ld_idx(edge_type, e, is64);
            int src = ld_idx(edge_index, e, is64);
            atomicAdd(&g_cnt[s * n_rel + r], 1.0f);
            const float4* xs = (const float4*)(x + (size_t)src * DIM);
            float* m = &g_msg[((size_t)s * n_rel + r) * DIM];
#pragma unroll
            for (int j = 0; j < DIM / 4; j++) {
                float4 v = xs[j];
                atomicAdd(&m[4 * j + 0], v.x);
                atomicAdd(&m[4 * j + 1], v.y);
                atomicAdd(&m[4 * j + 2], v.z);
                atomicAdd(&m[4 * j + 3], v.w);
            }
        }
    }
}

// ============ 3) k_gemm: prologue W staging | wait | compute ===============
// grid = (n_rel + 1) * 2 * GROUPS blocks of 128 threads. GROUPS=16 halves
// the per-block sequential slot-iterations (post-wait dependent chain).
__global__ void __launch_bounds__(128)
k_gemm(const float* __restrict__ W_rel,
       const float* __restrict__ W_root,
       const float* __restrict__ x,
       int n_rel) {
    pdl_trigger();                       // k_oc may start its prologue now
    __shared__ float Ws[64 * DIM];       // one 64-col half, Ws[d * 64 + c]
    __shared__ float ms[DIM];

    int idx  = blockIdx.x;
    int r    = idx % (n_rel + 1);
    int half = (idx / (n_rel + 1)) & 1;
    int sg   = idx / ((n_rel + 1) * 2);
    const float* W = (r < n_rel) ? (W_rel + (size_t)r * DIM * DIM) : W_root;
    int tid = threadIdx.x;

    // prologue: stage W tile (input-only; overlaps scan's whole body)
    int fbase = half * 64;
    for (int i = tid; i < 64 * DIM / 4; i += 128) {
        int d = i >> 4, c4 = i & 15;
        ((float4*)Ws)[d * 16 + c4] = *(const float4*)&W[d * DIM + fbase + c4 * 4];
    }
    __syncthreads();

    pdl_wait();                          // scan's msg/cnt/nn_copy now visible
    int nn = g_nn_copy;
    float* agg = g_agg[g_epoch & 1u];    // epoch stable since k_mark

    int c  = tid & 63;
    int dh = (tid >> 6) * 64;

    for (int s = sg; s < nn; s += GROUPS) {
        bool skip = false;
        float scale = 1.0f;
        if (r < n_rel) {
            float cnt = g_cnt[s * n_rel + r];    // uniform across block
            if (cnt == 0.0f) skip = true;
            else scale = 1.0f / cnt;
        }
        if (!skip) {
            if (r < n_rel)
                ms[tid] = g_msg[((size_t)s * n_rel + r) * DIM + tid] * scale;
            else
                ms[tid] = x[(size_t)g_needed_nodes[s] * DIM + tid];
        }
        __syncthreads();
        if (!skip) {
            float acc = 0.0f;
#pragma unroll
            for (int k = 0; k < 16; k++) {
                int d = dh + k * 4;
                float4 mv = *(const float4*)&ms[d];
                acc += mv.x * Ws[(d + 0) * 64 + c];
                acc += mv.y * Ws[(d + 1) * 64 + c];
                acc += mv.z * Ws[(d + 2) * 64 + c];
                acc += mv.w * Ws[(d + 3) * 64 + c];
            }
            atomicAdd(&agg[s * DIM + fbase + c], acc);
        }
        __syncthreads();
    }
}

// ============ 4) k_oc: prologue INPUT gathers | wait | out ∥ FULL cleanup ===
// Prologue reads ONLY inputs (sample for rel, init_rel). Post-wait, slots
// come from g_hs/g_ts (translated in k_scan), so g_slot/g_bits are never
// read here and can be zeroed concurrently with the output phase.
// grid = 256 blocks x 256 (batch warps).
__global__ void __launch_bounds__(256)
k_oc(const void* __restrict__ sample,
     const float* __restrict__ init_rel,
     float* __restrict__ out,
     int batch, int n_rel) {
    const int tid  = threadIdx.x;
    const int gtid = blockIdx.x * 256 + tid;
    const int gsz  = gridDim.x * 256;

    // prologue: dtype detect on sample + rel/init_rel gathers (inputs only)
    int is64;
    {
        unsigned int hw = ((const unsigned int*)sample)[((tid & 31) * 7 + 1) * 2 + 1];
        unsigned int any = __ballot_sync(0xffffffffu, hw != 0u);
        is64 = any ? 0 : 1;
    }
    int w    = gtid >> 5;
    int lane = tid & 31;
    float4 rv = make_float4(0.f, 0.f, 0.f, 0.f);
    if (w < batch) {
        int rel = 0;
        if (lane == 0) rel = ld_idx(sample, (size_t)w * 3 + 1, is64);
        rel = __shfl_sync(0xffffffffu, rel, 0);
        rv  = ((const float4*)init_rel)[rel * (DIM / 4) + lane];
    }

    pdl_wait();                          // gemm's agg + scan's hs/ts visible

    const int nn = g_nn_copy;
    const unsigned int par = g_epoch & 1u;

    // ---- out (slots from translated arrays; never touches g_slot) ---------
    if (w < batch) {
        int sh = 0, st = 0;
        if (lane == 0) { sh = g_hs[w]; st = g_ts[w]; }
        sh = __shfl_sync(0xffffffffu, sh, 0);
        st = __shfl_sync(0xffffffffu, st, 0);
        const float4* agg4 = (const float4*)g_agg[par];
        float4 ah = agg4[sh * (DIM / 4) + lane];
        float4 at = agg4[st * (DIM / 4) + lane];
        float4 o;
        o.x = ftanh(ah.x) * (rv.x * ftanh(at.x));
        o.y = ftanh(ah.y) * (rv.y * ftanh(at.y));
        o.z = ftanh(ah.z) * (rv.z * ftanh(at.z));
        o.w = ftanh(ah.w) * (rv.w * ftanh(at.w));
        ((float4*)out)[(size_t)w * (DIM / 4) + lane] = o;
    }

    // ---- full cleanup, concurrent with out (disjoint data) ----------------
    {
        float4 z = make_float4(0.f, 0.f, 0.f, 0.f);
        float4* msg4 = (float4*)g_msg;
        int n_msg4 = nn * n_rel * (DIM / 4);
        for (int i = gtid; i < n_msg4; i += gsz) msg4[i] = z;
        int n_cnt = nn * n_rel;
        for (int i = gtid; i < n_cnt; i += gsz) g_cnt[i] = 0.0f;
        float4* agg_next = (float4*)g_agg[1u - par];   // next call's buffer
        int n_agg4 = nn * (DIM / 4);
        for (int i = gtid; i < n_agg4; i += gsz) agg_next[i] = z;
        for (int i = gtid; i < nn; i += gsz) {
            int node = g_needed_nodes[i];
            g_slot[node] = 0;
            g_bits[node >> 5] = 0u;   // every set bit belongs to a needed node
        }
        if (gtid == 0) g_n_needed = 0;    // live counter; readers use g_nn_copy
    }
}

// ---------------- launch (PDL-chained) ----------------
template <typename... Args>
static inline void launch_pdl(void (*kern)(Args...), dim3 grid, dim3 block,
                              bool pdl_secondary, Args... args) {
    cudaLaunchConfig_t cfg = {};
    cfg.gridDim = grid;
    cfg.blockDim = block;
    cfg.dynamicSmemBytes = 0;
    cfg.stream = 0;
    cudaLaunchAttribute attr[1];
    if (pdl_secondary) {
        attr[0].id = cudaLaunchAttributeProgrammaticStreamSerialization;
        attr[0].val.programmaticStreamSerializationAllowed = 1;
        cfg.attrs = attr;
        cfg.numAttrs = 1;
    }
    cudaLaunchKernelEx(&cfg, kern, args...);
}

extern "C" void kernel_launch(void* const* d_in, const int* in_sizes, int n_in,
                              void* d_out, int out_size) {
    const float* init_embed = (const float*)d_in[0];
    const float* init_rel   = (const float*)d_in[1];
    const float* W_rel      = (const float*)d_in[2];
    const float* W_root     = (const float*)d_in[3];
    const void*  edge_index = d_in[4];
    const void*  edge_type  = d_in[5];
    const void*  sample     = d_in[6];
    float* out = (float*)d_out;

    int n_rel  = in_sizes[1] / DIM;
    int n_edge = in_sizes[5];
    int batch  = in_sizes[6] / 3;

    launch_pdl(k_mark, dim3((batch * 2 + 255) / 256), dim3(256), false,
               (const unsigned int*)edge_index, sample, batch);
    launch_pdl(k_scan, dim3((n_edge + EPT * 256 - 1) / (EPT * 256)), dim3(256), true,
               edge_index, edge_type, (const float*)init_embed, sample,
               n_edge, n_rel, batch);
    launch_pdl(k_gemm, dim3((n_rel + 1) * 2 * GROUPS), dim3(128), true,
               W_rel, W_root, (const float*)init_embed, n_rel);
    launch_pdl(k_oc, dim3(256), dim3(256), true,
               sample, (const float*)init_rel, out, batch, n_rel);
}